// round 14
// baseline (speedup 1.0000x reference)
#include <cuda_runtime.h>
#include <cstdint>

#define F_IN   256
#define F_OUT  32
#define CAP    64
#define N_MAX  100000

__device__ float4 g_h4[N_MAX * 8];       // h = x @ W (unscaled, fp32)
__device__ float  g_dinv[N_MAX];
__device__ int    g_cnt[N_MAX];
__device__ int    g_src[N_MAX * CAP];
__device__ int    g_is64;

// ---------------------------------------------------------------------------
// Edge pipeline (unchanged from the 92.3us configuration)
// ---------------------------------------------------------------------------
__global__ void k_detect(const void* __restrict__ ei, int n) {
    const long long* p = (const long long*)ei;
    int lane = threadIdx.x;
    long long v0 = p[lane], v1 = p[lane + 32];
    int ok = (v0 >= 0 && v0 < n) && (v1 >= 0 && v1 < n);
    ok = __all_sync(0xFFFFFFFFu, ok);
    if (lane == 0) g_is64 = ok;
}

__device__ __forceinline__ void fill_one(int src, int dst, int n) {
    if ((unsigned)src >= (unsigned)n || (unsigned)dst >= (unsigned)n) return;
    int slot = atomicAdd(&g_cnt[dst], 1);
    if (slot < CAP) g_src[dst * CAP + slot] = src;
}

__global__ void k_fill(const void* __restrict__ ei, int E, int n) {
    int t = blockIdx.x * blockDim.x + threadIdx.x;
    if (g_is64) {
        const long long* p = (const long long*)ei;
        for (int e = t * 4; e < E && e < t * 4 + 4; e++)
            fill_one((int)p[e], (int)p[E + e], n);
    } else {
        const int* p = (const int*)ei;
        int nv = E >> 2;
        if (t < nv) {
            int4 s4 = ((const int4*)p)[t];
            int4 d4 = ((const int4*)(p + E))[t];
            fill_one(s4.x, d4.x, n); fill_one(s4.y, d4.y, n);
            fill_one(s4.z, d4.z, n); fill_one(s4.w, d4.w, n);
        }
        if (t == 0)
            for (int e = nv * 4; e < E; e++) fill_one(p[e], p[E + e], n);
    }
}

__global__ void k_dinv(int n) {
    int i = blockIdx.x * blockDim.x + threadIdx.x;
    if (i < n) g_dinv[i] = rsqrtf((float)(g_cnt[i] + 1));
}

// ---------------------------------------------------------------------------
// TF32 helpers
// ---------------------------------------------------------------------------
__device__ __forceinline__ uint32_t f2tf32(float f) {
    uint32_t r;
    asm("cvt.rna.tf32.f32 %0, %1;" : "=r"(r) : "f"(f));
    return r;
}
__device__ __forceinline__ void mma_tf32(float* d, const uint32_t* a,
                                         uint32_t b0, uint32_t b1) {
    asm volatile(
        "mma.sync.aligned.m16n8k8.row.col.f32.tf32.tf32.f32 "
        "{%0,%1,%2,%3}, {%4,%5,%6,%7}, {%8,%9}, {%0,%1,%2,%3};"
        : "+f"(d[0]), "+f"(d[1]), "+f"(d[2]), "+f"(d[3])
        : "r"(a[0]), "r"(a[1]), "r"(a[2]), "r"(a[3]), "r"(b0), "r"(b1));
}

// ---------------------------------------------------------------------------
// GEMM: h[row,:] = x[row,:] @ W via 3xTF32 mma.sync (m16n8k8).
// 128 threads / 128 rows per block; warp = 32 rows x 32 cols
// (2 m-tiles x 4 n-tiles), K in 8 chunks of 32 (4 k-steps each).
// - B fragments (W^T in mma layout, tf32 hi/lo) materialized in smem once:
//   Bhi/Blo[(s*4+t)*32 + lane] = {b0,b1} -> one conflict-free LDS.64 per use.
// - A tile Xs[128][36] fp32 (stride 36 -> banks 4g+tg distinct, conflict-free);
//   hi/lo split done in registers (cvt.rna.tf32).
// - err: dropped lo*lo term ~2^-22 -> rel_err ~1e-6.
// ---------------------------------------------------------------------------
#define XS_STRIDE 36
#define SM_XS     0
#define SM_BHI    (128 * XS_STRIDE * 4)            // 18432
#define SM_BLO    (SM_BHI + 32768)                 // 51200
#define SM_TOTAL  (SM_BLO + 32768)                 // 83968

__global__ __launch_bounds__(128) void k_gemm(const float* __restrict__ x,
                                              const float* __restrict__ W,
                                              int n) {
    extern __shared__ char smem[];
    float*  Xs  = (float*)(smem + SM_XS);
    float2* Bhi = (float2*)(smem + SM_BHI);
    float2* Blo = (float2*)(smem + SM_BLO);

    const int tid  = threadIdx.x;
    const int lane = tid & 31;
    const int wid  = tid >> 5;
    const int g    = lane >> 2;     // group id (row within fragment)
    const int tg   = lane & 3;      // thread-in-group (k/col within fragment)
    const int row0 = blockIdx.x * 128;

    // ---- stage B fragments once: warp wid owns n-tile t=wid, all 32 k-steps ----
    for (int s = 0; s < 32; s++) {
        int kr = s * 8 + tg;
        int nc = wid * 8 + g;
        float w0 = W[(size_t)kr * F_OUT + nc];
        float w1 = W[(size_t)(kr + 4) * F_OUT + nc];
        uint32_t h0 = f2tf32(w0), h1 = f2tf32(w1);
        uint32_t l0 = f2tf32(w0 - __uint_as_float(h0));
        uint32_t l1 = f2tf32(w1 - __uint_as_float(h1));
        int idx = (s * 4 + wid) * 32 + lane;
        Bhi[idx] = make_float2(__uint_as_float(h0), __uint_as_float(h1));
        Blo[idx] = make_float2(__uint_as_float(l0), __uint_as_float(l1));
    }

    float d[2][4][4];
#pragma unroll
    for (int m = 0; m < 2; m++)
#pragma unroll
        for (int t = 0; t < 4; t++)
#pragma unroll
            for (int i = 0; i < 4; i++) d[m][t][i] = 0.0f;

    for (int ch = 0; ch < 8; ch++) {
        __syncthreads();   // prev chunk consumed (ch=0: B staging complete)

        // ---- stage Xs: task v = tid+128i -> row = v>>3, fq = v&7 (coalesced) ----
#pragma unroll
        for (int i = 0; i < 8; i++) {
            int v = tid + 128 * i;
            int row = v >> 3, fq = v & 7;
            int r = row0 + row;
            float4 xv = (r < n)
                ? *(const float4*)&x[(size_t)r * F_IN + ch * 32 + fq * 4]
                : make_float4(0.f, 0.f, 0.f, 0.f);
            *(float4*)&Xs[row * XS_STRIDE + fq * 4] = xv;
        }
        __syncthreads();

        // ---- 4 k-steps ----
#pragma unroll
        for (int j = 0; j < 4; j++) {
            int s = ch * 4 + j;
            float2 bh[4], bl[4];
#pragma unroll
            for (int t = 0; t < 4; t++) {
                bh[t] = Bhi[(s * 4 + t) * 32 + lane];
                bl[t] = Blo[(s * 4 + t) * 32 + lane];
            }
#pragma unroll
            for (int m = 0; m < 2; m++) {
                int rb = wid * 32 + m * 16;
                float x0 = Xs[(rb + g) * XS_STRIDE + j * 8 + tg];
                float x1 = Xs[(rb + g + 8) * XS_STRIDE + j * 8 + tg];
                float x2 = Xs[(rb + g) * XS_STRIDE + j * 8 + tg + 4];
                float x3 = Xs[(rb + g + 8) * XS_STRIDE + j * 8 + tg + 4];
                uint32_t ah[4], al[4];
                ah[0] = f2tf32(x0); al[0] = f2tf32(x0 - __uint_as_float(ah[0]));
                ah[1] = f2tf32(x1); al[1] = f2tf32(x1 - __uint_as_float(ah[1]));
                ah[2] = f2tf32(x2); al[2] = f2tf32(x2 - __uint_as_float(ah[2]));
                ah[3] = f2tf32(x3); al[3] = f2tf32(x3 - __uint_as_float(ah[3]));
#pragma unroll
                for (int t = 0; t < 4; t++) {
                    uint32_t bh0 = __float_as_uint(bh[t].x);
                    uint32_t bh1 = __float_as_uint(bh[t].y);
                    uint32_t bl0 = __float_as_uint(bl[t].x);
                    uint32_t bl1 = __float_as_uint(bl[t].y);
                    mma_tf32(d[m][t], ah, bh0, bh1);   // hi*hi
                    mma_tf32(d[m][t], al, bh0, bh1);   // lo*hi
                    mma_tf32(d[m][t], ah, bl0, bl1);   // hi*lo
                }
            }
        }
    }

    // ---- epilogue: D[r][c]: r = row0+wid*32+m*16+g(+8), c = t*8+2tg(+1) ----
    float2* out2 = (float2*)g_h4;
#pragma unroll
    for (int m = 0; m < 2; m++) {
        int r0 = row0 + wid * 32 + m * 16 + g;
        int r1 = r0 + 8;
#pragma unroll
        for (int t = 0; t < 4; t++) {
            if (r0 < n)
                out2[(size_t)r0 * 16 + t * 4 + tg] = make_float2(d[m][t][0], d[m][t][1]);
            if (r1 < n)
                out2[(size_t)r1 * 16 + t * 4 + tg] = make_float2(d[m][t][2], d[m][t][3]);
        }
    }
}

// ---------------------------------------------------------------------------
// Gather (unchanged from 92.3us config)
// ---------------------------------------------------------------------------
__global__ void k_gather(const float* __restrict__ b,
                         float4* __restrict__ out, int n) {
    int gid = blockIdx.x * blockDim.x + threadIdx.x;
    int i = gid >> 3;
    int q = gid & 7;
    if (i >= n) return;

    float di = g_dinv[i];
    float4 h = g_h4[(size_t)i * 8 + q];
    float4 acc = make_float4(h.x * di, h.y * di, h.z * di, h.w * di);

    int cnt = g_cnt[i];
    if (cnt > CAP) cnt = CAP;
    const int* lst = &g_src[i * CAP];
    for (int k = 0; k < cnt; k++) {
        int src = lst[k];
        float nr = g_dinv[src];
        float4 v = g_h4[(size_t)src * 8 + q];
        acc.x += v.x * nr; acc.y += v.y * nr;
        acc.z += v.z * nr; acc.w += v.w * nr;
    }

    float4 bq = ((const float4*)b)[q];
    float4 o;
    o.x = bq.x + di * acc.x;
    o.y = bq.y + di * acc.y;
    o.z = bq.z + di * acc.z;
    o.w = bq.w + di * acc.w;
    out[(size_t)i * 8 + q] = o;

    int lane = threadIdx.x & 31;
    unsigned mask = 0xFFu << (lane & ~7);
    __syncwarp(mask);
    if (q == 0) g_cnt[i] = 0;
}

// ---------------------------------------------------------------------------
extern "C" void kernel_launch(void* const* d_in, const int* in_sizes, int n_in,
                              void* d_out, int out_size) {
    const float* x  = (const float*)d_in[0];
    const void*  ei = d_in[1];
    const float* W  = (const float*)d_in[2];
    const float* b  = (const float*)d_in[3];
    float4* out = (float4*)d_out;

    const int n = in_sizes[0] / F_IN;
    const int E = in_sizes[1] / 2;

    const int gemm_grid   = (n + 127) / 128;
    const int fill_grid   = ((E + 3) / 4 + 255) / 256;
    const int dinv_grid   = (n + 255) / 256;
    const int gather_grid = (int)(((long long)n * 8 + 255) / 256);

    static bool attr_set = false;
    if (!attr_set) {
        cudaFuncSetAttribute(k_gemm, cudaFuncAttributeMaxDynamicSharedMemorySize,
                             SM_TOTAL);
        attr_set = true;
    }

    static cudaStream_t sB = nullptr;
    static cudaEvent_t  eF = nullptr, eJ = nullptr;
    if (sB == nullptr) {
        if (cudaStreamCreateWithFlags(&sB, cudaStreamNonBlocking) != cudaSuccess)
            sB = nullptr;
        if (sB) {
            cudaEventCreateWithFlags(&eF, cudaEventDisableTiming);
            cudaEventCreateWithFlags(&eJ, cudaEventDisableTiming);
        }
    }

    if (sB) {
        cudaEventRecord(eF, 0);
        cudaStreamWaitEvent(sB, eF, 0);
        k_gemm<<<gemm_grid, 128, SM_TOTAL, sB>>>(x, W, n);

        k_detect<<<1, 32>>>(ei, n);
        k_fill<<<fill_grid, 256>>>(ei, E, n);
        k_dinv<<<dinv_grid, 256>>>(n);

        cudaEventRecord(eJ, sB);
        cudaStreamWaitEvent(0, eJ, 0);
        k_gather<<<gather_grid, 256>>>(b, out, n);
    } else {
        k_detect<<<1, 32>>>(ei, n);
        k_fill<<<fill_grid, 256>>>(ei, E, n);
        k_dinv<<<dinv_grid, 256>>>(n);
        k_gemm<<<gemm_grid, 128, SM_TOTAL>>>(x, W, n);
        k_gather<<<gather_grid, 256>>>(b, out, n);
    }
}

// round 15
// speedup vs baseline: 1.0135x; 1.0135x over previous
#include <cuda_runtime.h>
#include <cstdint>

#define F_IN   256
#define F_OUT  32
#define CAP    64
#define N_MAX  100000

__device__ float4 g_h4[N_MAX * 8];       // h = x @ W (unscaled, fp32)
__device__ float  g_dinv[N_MAX];
__device__ int    g_cnt[N_MAX];
__device__ int    g_src[N_MAX * CAP];
__device__ int    g_is64;

// ---------------------------------------------------------------------------
// Edge pipeline (unchanged from the 92.3us configuration)
// ---------------------------------------------------------------------------
__global__ void k_detect(const void* __restrict__ ei, int n) {
    const long long* p = (const long long*)ei;
    int lane = threadIdx.x;
    long long v0 = p[lane], v1 = p[lane + 32];
    int ok = (v0 >= 0 && v0 < n) && (v1 >= 0 && v1 < n);
    ok = __all_sync(0xFFFFFFFFu, ok);
    if (lane == 0) g_is64 = ok;
}

__device__ __forceinline__ void fill_one(int src, int dst, int n) {
    if ((unsigned)src >= (unsigned)n || (unsigned)dst >= (unsigned)n) return;
    int slot = atomicAdd(&g_cnt[dst], 1);
    if (slot < CAP) g_src[dst * CAP + slot] = src;
}

__global__ void k_fill(const void* __restrict__ ei, int E, int n) {
    int t = blockIdx.x * blockDim.x + threadIdx.x;
    if (g_is64) {
        const long long* p = (const long long*)ei;
        for (int e = t * 4; e < E && e < t * 4 + 4; e++)
            fill_one((int)p[e], (int)p[E + e], n);
    } else {
        const int* p = (const int*)ei;
        int nv = E >> 2;
        if (t < nv) {
            int4 s4 = ((const int4*)p)[t];
            int4 d4 = ((const int4*)(p + E))[t];
            fill_one(s4.x, d4.x, n); fill_one(s4.y, d4.y, n);
            fill_one(s4.z, d4.z, n); fill_one(s4.w, d4.w, n);
        }
        if (t == 0)
            for (int e = nv * 4; e < E; e++) fill_one(p[e], p[E + e], n);
    }
}

__global__ void k_dinv(int n) {
    int i = blockIdx.x * blockDim.x + threadIdx.x;
    if (i < n) g_dinv[i] = rsqrtf((float)(g_cnt[i] + 1));
}

// ---------------------------------------------------------------------------
// bf16 helpers
// ---------------------------------------------------------------------------
// pack {low16 = bf16(flo), high16 = bf16(fhi)}  (PTX: d.hi = cvt(a), d.lo = cvt(b))
__device__ __forceinline__ uint32_t pack_bf16x2(float flo, float fhi) {
    uint32_t r;
    asm("cvt.rn.bf16x2.f32 %0, %1, %2;" : "=r"(r) : "f"(fhi), "f"(flo));
    return r;
}
// recover fp32 values of the two packed bf16 halves
__device__ __forceinline__ float bf16lo_f(uint32_t u) { return __uint_as_float(u << 16); }
__device__ __forceinline__ float bf16hi_f(uint32_t u) { return __uint_as_float(u & 0xFFFF0000u); }

__device__ __forceinline__ void mma_bf16(float* d, const uint32_t* a,
                                         uint32_t b0, uint32_t b1) {
    asm volatile(
        "mma.sync.aligned.m16n8k16.row.col.f32.bf16.bf16.f32 "
        "{%0,%1,%2,%3}, {%4,%5,%6,%7}, {%8,%9}, {%0,%1,%2,%3};"
        : "+f"(d[0]), "+f"(d[1]), "+f"(d[2]), "+f"(d[3])
        : "r"(a[0]), "r"(a[1]), "r"(a[2]), "r"(a[3]), "r"(b0), "r"(b1));
}

// ---------------------------------------------------------------------------
// GEMM: h = x @ W via 3-term bf16 split on mma.sync.m16n8k16 (sm_80+ path;
// tcgen05 is ptxas-rejected on target sm_103). R14's tf32 k8 version was
// HMMA-issue-bound (~30 cyc/SMSP legacy rate) -> k16 halves the HMMA count,
// and A's bf16 conversion moves to the staging phase (inner loop = LDS+HMMA).
// 128 threads / 128 rows per block; warp = 32 rows x 32 cols; 8 K-chunks of 32.
// Xhi/Xlo: packed bf16x2 pairs, row stride 20 -> fragment LDS.32 conflict-free.
// Bhi/Blo: fragment-layout uint2 {b0,b1}, one LDS.64 per (k-step, tile).
// err: dropped lo*lo ~2^-16 -> rel_err ~1e-5 (gate 1e-3).
// ---------------------------------------------------------------------------
#define XR        20                                  // uint32 pairs per row (16+4 pad)
#define SM_XHI    0
#define SM_XLO    (128 * XR * 4)                      // 10240
#define SM_BHI    (SM_XLO + 128 * XR * 4)             // 20480
#define SM_BLO    (SM_BHI + 16384)                    // 36864
#define SM_TOTAL  (SM_BLO + 16384)                    // 53248

__global__ __launch_bounds__(128) void k_gemm(const float* __restrict__ x,
                                              const float* __restrict__ W,
                                              int n) {
    extern __shared__ char smem[];
    uint32_t* Xhi = (uint32_t*)(smem + SM_XHI);
    uint32_t* Xlo = (uint32_t*)(smem + SM_XLO);
    uint2*    Bhi = (uint2*)(smem + SM_BHI);
    uint2*    Blo = (uint2*)(smem + SM_BLO);

    const int tid  = threadIdx.x;
    const int lane = tid & 31;
    const int wid  = tid >> 5;
    const int g    = lane >> 2;     // fragment row / B col
    const int tg   = lane & 3;      // fragment k group
    const int row0 = blockIdx.x * 128;

    // ---- stage B fragments once: warp wid owns n-tile t=wid, 16 k-steps ----
    for (int s = 0; s < 16; s++) {
        int kr = s * 16;
        int nc = wid * 8 + g;
        float w0 = W[(size_t)(kr + 2 * tg)     * F_OUT + nc];
        float w1 = W[(size_t)(kr + 2 * tg + 1) * F_OUT + nc];
        float w2 = W[(size_t)(kr + 2 * tg + 8) * F_OUT + nc];
        float w3 = W[(size_t)(kr + 2 * tg + 9) * F_OUT + nc];
        uint32_t b0h = pack_bf16x2(w0, w1);
        uint32_t b1h = pack_bf16x2(w2, w3);
        uint32_t b0l = pack_bf16x2(w0 - bf16lo_f(b0h), w1 - bf16hi_f(b0h));
        uint32_t b1l = pack_bf16x2(w2 - bf16lo_f(b1h), w3 - bf16hi_f(b1h));
        int idx = (s * 4 + wid) * 32 + lane;
        Bhi[idx] = make_uint2(b0h, b1h);
        Blo[idx] = make_uint2(b0l, b1l);
    }

    float d[2][4][4];
#pragma unroll
    for (int m = 0; m < 2; m++)
#pragma unroll
        for (int t = 0; t < 4; t++)
#pragma unroll
            for (int i = 0; i < 4; i++) d[m][t][i] = 0.0f;

    for (int ch = 0; ch < 8; ch++) {
        __syncthreads();   // prev chunk consumed (ch=0: B staging complete)

        // ---- stage A chunk: task v = tid+128i -> row=v>>3, fq=v&7; convert
        //      float4 -> 2 packed bf16x2 pairs (hi & lo) ----
#pragma unroll
        for (int i = 0; i < 8; i++) {
            int v = tid + 128 * i;
            int row = v >> 3, fq = v & 7;
            int r = row0 + row;
            float4 xv = (r < n)
                ? *(const float4*)&x[(size_t)r * F_IN + ch * 32 + fq * 4]
                : make_float4(0.f, 0.f, 0.f, 0.f);
            uint32_t h0 = pack_bf16x2(xv.x, xv.y);
            uint32_t h1 = pack_bf16x2(xv.z, xv.w);
            uint32_t l0 = pack_bf16x2(xv.x - bf16lo_f(h0), xv.y - bf16hi_f(h0));
            uint32_t l1 = pack_bf16x2(xv.z - bf16lo_f(h1), xv.w - bf16hi_f(h1));
            *(uint2*)&Xhi[row * XR + fq * 2] = make_uint2(h0, h1);
            *(uint2*)&Xlo[row * XR + fq * 2] = make_uint2(l0, l1);
        }
        __syncthreads();

        // ---- 2 k-steps of 16 ----
#pragma unroll
        for (int jj = 0; jj < 2; jj++) {
            int s = ch * 2 + jj;
            int pb = jj * 8 + tg;          // local pair base for a0/a1
            uint32_t ah[4], al[4];
#pragma unroll
            for (int m = 0; m < 2; m++) {
                int r_g  = (wid * 32 + m * 16 + g) * XR;
                int r_g8 = r_g + 8 * XR;
                ah[0] = Xhi[r_g  + pb];     al[0] = Xlo[r_g  + pb];
                ah[1] = Xhi[r_g8 + pb];     al[1] = Xlo[r_g8 + pb];
                ah[2] = Xhi[r_g  + pb + 4]; al[2] = Xlo[r_g  + pb + 4];
                ah[3] = Xhi[r_g8 + pb + 4]; al[3] = Xlo[r_g8 + pb + 4];
#pragma unroll
                for (int t = 0; t < 4; t++) {
                    uint2 bh = Bhi[(s * 4 + t) * 32 + lane];
                    uint2 bl = Blo[(s * 4 + t) * 32 + lane];
                    mma_bf16(d[m][t], ah, bh.x, bh.y);   // hi*hi
                    mma_bf16(d[m][t], al, bh.x, bh.y);   // lo*hi
                    mma_bf16(d[m][t], ah, bl.x, bl.y);   // hi*lo
                }
            }
        }
    }

    // ---- epilogue: D[r][c]: r = row0+wid*32+m*16+g(+8), c = t*8+2tg(+1) ----
    float2* out2 = (float2*)g_h4;
#pragma unroll
    for (int m = 0; m < 2; m++) {
        int r0 = row0 + wid * 32 + m * 16 + g;
        int r1 = r0 + 8;
#pragma unroll
        for (int t = 0; t < 4; t++) {
            if (r0 < n)
                out2[(size_t)r0 * 16 + t * 4 + tg] = make_float2(d[m][t][0], d[m][t][1]);
            if (r1 < n)
                out2[(size_t)r1 * 16 + t * 4 + tg] = make_float2(d[m][t][2], d[m][t][3]);
        }
    }
}

// ---------------------------------------------------------------------------
// Gather (unchanged from 92.3us config)
// ---------------------------------------------------------------------------
__global__ void k_gather(const float* __restrict__ b,
                         float4* __restrict__ out, int n) {
    int gid = blockIdx.x * blockDim.x + threadIdx.x;
    int i = gid >> 3;
    int q = gid & 7;
    if (i >= n) return;

    float di = g_dinv[i];
    float4 h = g_h4[(size_t)i * 8 + q];
    float4 acc = make_float4(h.x * di, h.y * di, h.z * di, h.w * di);

    int cnt = g_cnt[i];
    if (cnt > CAP) cnt = CAP;
    const int* lst = &g_src[i * CAP];
    for (int k = 0; k < cnt; k++) {
        int src = lst[k];
        float nr = g_dinv[src];
        float4 v = g_h4[(size_t)src * 8 + q];
        acc.x += v.x * nr; acc.y += v.y * nr;
        acc.z += v.z * nr; acc.w += v.w * nr;
    }

    float4 bq = ((const float4*)b)[q];
    float4 o;
    o.x = bq.x + di * acc.x;
    o.y = bq.y + di * acc.y;
    o.z = bq.z + di * acc.z;
    o.w = bq.w + di * acc.w;
    out[(size_t)i * 8 + q] = o;

    int lane = threadIdx.x & 31;
    unsigned mask = 0xFFu << (lane & ~7);
    __syncwarp(mask);
    if (q == 0) g_cnt[i] = 0;
}

// ---------------------------------------------------------------------------
extern "C" void kernel_launch(void* const* d_in, const int* in_sizes, int n_in,
                              void* d_out, int out_size) {
    const float* x  = (const float*)d_in[0];
    const void*  ei = d_in[1];
    const float* W  = (const float*)d_in[2];
    const float* b  = (const float*)d_in[3];
    float4* out = (float4*)d_out;

    const int n = in_sizes[0] / F_IN;
    const int E = in_sizes[1] / 2;

    const int gemm_grid   = (n + 127) / 128;
    const int fill_grid   = ((E + 3) / 4 + 255) / 256;
    const int dinv_grid   = (n + 255) / 256;
    const int gather_grid = (int)(((long long)n * 8 + 255) / 256);

    static bool attr_set = false;
    if (!attr_set) {
        cudaFuncSetAttribute(k_gemm, cudaFuncAttributeMaxDynamicSharedMemorySize,
                             SM_TOTAL);
        attr_set = true;
    }

    static cudaStream_t sB = nullptr;
    static cudaEvent_t  eF = nullptr, eJ = nullptr;
    if (sB == nullptr) {
        if (cudaStreamCreateWithFlags(&sB, cudaStreamNonBlocking) != cudaSuccess)
            sB = nullptr;
        if (sB) {
            cudaEventCreateWithFlags(&eF, cudaEventDisableTiming);
            cudaEventCreateWithFlags(&eJ, cudaEventDisableTiming);
        }
    }

    if (sB) {
        cudaEventRecord(eF, 0);
        cudaStreamWaitEvent(sB, eF, 0);
        k_gemm<<<gemm_grid, 128, SM_TOTAL, sB>>>(x, W, n);

        k_detect<<<1, 32>>>(ei, n);
        k_fill<<<fill_grid, 256>>>(ei, E, n);
        k_dinv<<<dinv_grid, 256>>>(n);

        cudaEventRecord(eJ, sB);
        cudaStreamWaitEvent(0, eJ, 0);
        k_gather<<<gather_grid, 256>>>(b, out, n);
    } else {
        k_detect<<<1, 32>>>(ei, n);
        k_fill<<<fill_grid, 256>>>(ei, E, n);
        k_dinv<<<dinv_grid, 256>>>(n);
        k_gemm<<<gemm_grid, 128, SM_TOTAL>>>(x, W, n);
        k_gather<<<gather_grid, 256>>>(b, out, n);
    }
}

// round 16
// speedup vs baseline: 1.1226x; 1.1076x over previous
#include <cuda_runtime.h>
#include <cstdint>

#define F_IN   256
#define F_OUT  32
#define CAP    64
#define N_MAX  100000

__device__ float4 g_h4[N_MAX * 8];       // h = x @ W (unscaled, fp32)
__device__ float  g_dinv[N_MAX];
__device__ int    g_cnt[N_MAX];
__device__ int    g_src[N_MAX * CAP];
__device__ int    g_is64;

// ---------------------------------------------------------------------------
// f32x2 helpers (Blackwell packed fp32)
// ---------------------------------------------------------------------------
__device__ __forceinline__ unsigned long long pack2(float lo, float hi) {
    unsigned long long r;
    asm("mov.b64 %0, {%1, %2};" : "=l"(r) : "f"(lo), "f"(hi));
    return r;
}
__device__ __forceinline__ void unpack2(unsigned long long v, float& lo, float& hi) {
    asm("mov.b64 {%0, %1}, %2;" : "=f"(lo), "=f"(hi) : "l"(v));
}
__device__ __forceinline__ void ffma2(unsigned long long& d,
                                      unsigned long long a,
                                      unsigned long long b) {
    asm("fma.rn.f32x2 %0, %1, %2, %0;" : "+l"(d) : "l"(a), "l"(b));
}

// ---------------------------------------------------------------------------
// Edge pipeline (unchanged from the 92.3us configuration)
// ---------------------------------------------------------------------------
__global__ void k_detect(const void* __restrict__ ei, int n) {
    const long long* p = (const long long*)ei;
    int lane = threadIdx.x;
    long long v0 = p[lane], v1 = p[lane + 32];
    int ok = (v0 >= 0 && v0 < n) && (v1 >= 0 && v1 < n);
    ok = __all_sync(0xFFFFFFFFu, ok);
    if (lane == 0) g_is64 = ok;
}

__device__ __forceinline__ void fill_one(int src, int dst, int n) {
    if ((unsigned)src >= (unsigned)n || (unsigned)dst >= (unsigned)n) return;
    int slot = atomicAdd(&g_cnt[dst], 1);
    if (slot < CAP) g_src[dst * CAP + slot] = src;
}

__global__ void k_fill(const void* __restrict__ ei, int E, int n) {
    int t = blockIdx.x * blockDim.x + threadIdx.x;
    if (g_is64) {
        const long long* p = (const long long*)ei;
        for (int e = t * 4; e < E && e < t * 4 + 4; e++)
            fill_one((int)p[e], (int)p[E + e], n);
    } else {
        const int* p = (const int*)ei;
        int nv = E >> 2;
        if (t < nv) {
            int4 s4 = ((const int4*)p)[t];
            int4 d4 = ((const int4*)(p + E))[t];
            fill_one(s4.x, d4.x, n); fill_one(s4.y, d4.y, n);
            fill_one(s4.z, d4.z, n); fill_one(s4.w, d4.w, n);
        }
        if (t == 0)
            for (int e = nv * 4; e < E; e++) fill_one(p[e], p[E + e], n);
    }
}

__global__ void k_dinv(int n) {
    int i = blockIdx.x * blockDim.x + threadIdx.x;
    if (i < n) g_dinv[i] = rsqrtf((float)(g_cnt[i] + 1));
}

// ---------------------------------------------------------------------------
// GEMM: h[row,:] = x[row,:] @ W  (unscaled; concurrent with the fill branch).
// Clean warp-count test vs the 92.3us R9 baseline:
//   - compute structure: 256 threads / 256 rows, thread = 4 rows x 8 cols
//     (2 f32x2 pairs), conflict-free LDS.64 X reads + LDS.128 W broadcasts
//     (identical to R12, which was numerically correct);
//   - staging map: R9's high-quality one (sj=tid>>2, fq=tid&3 -> each warp
//     LDG.128 touches 8 lines; R12's map touched 16 -> its regression).
// Result: 5.3 warps/SMSP (vs R9's 2.64) with equal staging wavefronts/tile.
// ---------------------------------------------------------------------------
#define KK_TILE 16
#define XPAD    130   // float2 per kk row (128 pairs + 2 pad)
#define WPAD    34    // u64 per kk row (32 + 2 pad)

__global__ __launch_bounds__(256) void k_gemm(const float* __restrict__ x,
                                              const float* __restrict__ W,
                                              int n) {
    __shared__ alignas(16) float2             Xs2[KK_TILE][XPAD];   // 16.6 KB
    __shared__ alignas(16) unsigned long long Ws2[KK_TILE][WPAD];   //  4.4 KB

    const int tid  = threadIdx.x;
    const int lane = tid & 31;
    const int wg   = tid >> 5;        // 0..7
    const int half = wg >> 2;         // 0/1 -> pair range base 64*half
    const int wp   = wg & 3;          // col base wp*8
    const int row0 = blockIdx.x * 256;

    // staging maps (R9 quality): X task q in {0,1}: pair j = sj + 64q
    const int sj  = tid >> 2;         // pair 0..63
    const int fq  = tid & 3;          // float4 within the 16-k chunk
    const int wkk = tid >> 4;         // W: kk 0..15
    const int wc2 = tid & 15;         // W: col pair (2 cols)

    unsigned long long acc[2][8];
#pragma unroll
    for (int p = 0; p < 2; p++)
#pragma unroll
        for (int c = 0; c < 8; c++) acc[p][c] = 0ull;

    for (int t = 0; t < F_IN / KK_TILE; t++) {
        const int k0 = t * KK_TILE;
        __syncthreads();   // previous tile fully consumed

        // --- stage X: 2 tasks, each = one row-pair x 4 k-values ---
        // Warp per v0-load: 8 rows x 64B contiguous -> 8 lines per LDG.128.
#pragma unroll
        for (int q = 0; q < 2; q++) {
            int j   = sj + 64 * q;            // pair 0..127
            int rlo = row0 + 2 * j;
            float4 v0 = (rlo < n)
                ? *(const float4*)&x[(size_t)rlo * F_IN + k0 + fq * 4]
                : make_float4(0.f, 0.f, 0.f, 0.f);
            float4 v1 = (rlo + 1 < n)
                ? *(const float4*)&x[(size_t)(rlo + 1) * F_IN + k0 + fq * 4]
                : make_float4(0.f, 0.f, 0.f, 0.f);
            Xs2[fq * 4 + 0][j] = make_float2(v0.x, v1.x);
            Xs2[fq * 4 + 1][j] = make_float2(v0.y, v1.y);
            Xs2[fq * 4 + 2][j] = make_float2(v0.z, v1.z);
            Xs2[fq * 4 + 3][j] = make_float2(v0.w, v1.w);
        }
        // --- stage W (pre-packed {w,w}; warp covers 2 kk rows, coalesced) ---
        {
            float2 w = *(const float2*)&W[(size_t)(k0 + wkk) * F_OUT + wc2 * 2];
            Ws2[wkk][wc2 * 2 + 0] = pack2(w.x, w.x);
            Ws2[wkk][wc2 * 2 + 1] = pack2(w.y, w.y);
        }
        __syncthreads();

        // --- compute ---
#pragma unroll
        for (int kk = 0; kk < KK_TILE; kk++) {
            unsigned long long xv[2];
#pragma unroll
            for (int p = 0; p < 2; p++)
                xv[p] = *(const unsigned long long*)
                            &Xs2[kk][lane + 32 * p + 64 * half];
            const ulonglong2* wr = (const ulonglong2*)&Ws2[kk][wp * 8];
#pragma unroll
            for (int c2 = 0; c2 < 4; c2++) {
                ulonglong2 w2 = wr[c2];                 // LDS.128 broadcast
                ffma2(acc[0][2 * c2 + 0], xv[0], w2.x);
                ffma2(acc[0][2 * c2 + 1], xv[0], w2.y);
                ffma2(acc[1][2 * c2 + 0], xv[1], w2.x);
                ffma2(acc[1][2 * c2 + 1], xv[1], w2.y);
            }
        }
    }

    // Epilogue: pairs j = lane + 32p + 64*half; cols wp*8..wp*8+7 (unscaled h).
#pragma unroll
    for (int p = 0; p < 2; p++) {
        int j   = lane + 32 * p + 64 * half;
        int rlo = row0 + 2 * j;
        int rhi = rlo + 1;
        float lo[8], hi[8];
#pragma unroll
        for (int c = 0; c < 8; c++) unpack2(acc[p][c], lo[c], hi[c]);
        if (rlo < n) {
            g_h4[(size_t)rlo * 8 + wp * 2 + 0] = make_float4(lo[0], lo[1], lo[2], lo[3]);
            g_h4[(size_t)rlo * 8 + wp * 2 + 1] = make_float4(lo[4], lo[5], lo[6], lo[7]);
        }
        if (rhi < n) {
            g_h4[(size_t)rhi * 8 + wp * 2 + 0] = make_float4(hi[0], hi[1], hi[2], hi[3]);
            g_h4[(size_t)rhi * 8 + wp * 2 + 1] = make_float4(hi[4], hi[5], hi[6], hi[7]);
        }
    }
}

// ---------------------------------------------------------------------------
// Gather (unchanged from 92.3us config)
// ---------------------------------------------------------------------------
__global__ void k_gather(const float* __restrict__ b,
                         float4* __restrict__ out, int n) {
    int gid = blockIdx.x * blockDim.x + threadIdx.x;
    int i = gid >> 3;
    int q = gid & 7;
    if (i >= n) return;

    float di = g_dinv[i];
    float4 h = g_h4[(size_t)i * 8 + q];
    float4 acc = make_float4(h.x * di, h.y * di, h.z * di, h.w * di);

    int cnt = g_cnt[i];
    if (cnt > CAP) cnt = CAP;
    const int* lst = &g_src[i * CAP];
    for (int k = 0; k < cnt; k++) {
        int src = lst[k];
        float nr = g_dinv[src];
        float4 v = g_h4[(size_t)src * 8 + q];
        acc.x += v.x * nr; acc.y += v.y * nr;
        acc.z += v.z * nr; acc.w += v.w * nr;
    }

    float4 bq = ((const float4*)b)[q];
    float4 o;
    o.x = bq.x + di * acc.x;
    o.y = bq.y + di * acc.y;
    o.z = bq.z + di * acc.z;
    o.w = bq.w + di * acc.w;
    out[(size_t)i * 8 + q] = o;

    int lane = threadIdx.x & 31;
    unsigned mask = 0xFFu << (lane & ~7);
    __syncwarp(mask);
    if (q == 0) g_cnt[i] = 0;
}

// ---------------------------------------------------------------------------
extern "C" void kernel_launch(void* const* d_in, const int* in_sizes, int n_in,
                              void* d_out, int out_size) {
    const float* x  = (const float*)d_in[0];
    const void*  ei = d_in[1];
    const float* W  = (const float*)d_in[2];
    const float* b  = (const float*)d_in[3];
    float4* out = (float4*)d_out;

    const int n = in_sizes[0] / F_IN;
    const int E = in_sizes[1] / 2;

    const int gemm_grid   = (n + 255) / 256;
    const int fill_grid   = ((E + 3) / 4 + 255) / 256;
    const int dinv_grid   = (n + 255) / 256;
    const int gather_grid = (int)(((long long)n * 8 + 255) / 256);

    static cudaStream_t sB = nullptr;
    static cudaEvent_t  eF = nullptr, eJ = nullptr;
    if (sB == nullptr) {
        if (cudaStreamCreateWithFlags(&sB, cudaStreamNonBlocking) != cudaSuccess)
            sB = nullptr;
        if (sB) {
            cudaEventCreateWithFlags(&eF, cudaEventDisableTiming);
            cudaEventCreateWithFlags(&eJ, cudaEventDisableTiming);
        }
    }

    if (sB) {
        cudaEventRecord(eF, 0);
        cudaStreamWaitEvent(sB, eF, 0);
        k_gemm<<<gemm_grid, 256, 0, sB>>>(x, W, n);

        k_detect<<<1, 32>>>(ei, n);
        k_fill<<<fill_grid, 256>>>(ei, E, n);
        k_dinv<<<dinv_grid, 256>>>(n);

        cudaEventRecord(eJ, sB);
        cudaStreamWaitEvent(0, eJ, 0);
        k_gather<<<gather_grid, 256>>>(b, out, n);
    } else {
        k_detect<<<1, 32>>>(ei, n);
        k_fill<<<fill_grid, 256>>>(ei, E, n);
        k_dinv<<<dinv_grid, 256>>>(n);
        k_gemm<<<gemm_grid, 256>>>(x, W, n);
        k_gather<<<gather_grid, 256>>>(b, out, n);
    }
}